// round 1
// baseline (speedup 1.0000x reference)
#include <cuda_runtime.h>
#include <cuda_bf16.h>
#include <cstdint>

// Batched inverse of 3x3 upper-triangular matrices.
// Input rows: [a b c | . d e | . . f]  (elements 3,6,7 ignored)
// Output rows (row-major 3x3):
//   [ 1/a  -b/(ad)  (be-cd)/(adf) ]
//   [  0     1/d      -e/(df)     ]
//   [  0      0         1/f       ]
//
// Strategy: DRAM-bound elementwise op. Stage 1024 rows (9216 floats = 2304
// float4) per 256-thread block through shared memory so all global traffic is
// LDG.128 / STG.128 fully coalesced. Compute phase maps thread t to rows
// {t, t+256, t+512, t+768}: word address 9*t + k, gcd(9,32)=1 -> conflict-free
// scalar LDS/STS.

#define THREADS 256
#define ROWS_PER_BLOCK 1024
#define FLOATS_PER_BLOCK (ROWS_PER_BLOCK * 9)          // 9216
#define VEC_PER_BLOCK (FLOATS_PER_BLOCK / 4)           // 2304
#define VEC_PER_THREAD (VEC_PER_BLOCK / THREADS)       // 9

__global__ __launch_bounds__(THREADS) void inv3_vec_kernel(
    const float4* __restrict__ in, float4* __restrict__ out)
{
    __shared__ float s[FLOATS_PER_BLOCK];  // 36 KB

    const long long base_vec = (long long)blockIdx.x * VEC_PER_BLOCK;

    // ---- Stage in: 9 coalesced float4 loads per thread ----
    float4* sv = reinterpret_cast<float4*>(s);
#pragma unroll
    for (int i = 0; i < VEC_PER_THREAD; i++) {
        int li = threadIdx.x + i * THREADS;
        sv[li] = in[base_vec + li];
    }
    __syncthreads();

    // ---- Compute: 4 rows per thread, stride-256 row mapping ----
#pragma unroll
    for (int r = 0; r < 4; r++) {
        int row = threadIdx.x + r * THREADS;
        float* p = &s[row * 9];
        float a = p[0], b = p[1], c = p[2];
        float d = p[4], e = p[5];
        float f = p[8];

        float ia  = __frcp_rn(a);
        float id  = __frcp_rn(d);
        float iff = __frcp_rn(f);

        float iad   = ia * id;
        float o01   = -b * iad;
        float o12   = -e * (id * iff);
        float o02   = (b * e - c * d) * (iad * iff);

        p[0] = ia;
        p[1] = o01;
        p[2] = o02;
        p[3] = 0.0f;
        p[4] = id;
        p[5] = o12;
        p[6] = 0.0f;
        p[7] = 0.0f;
        p[8] = iff;
    }
    __syncthreads();

    // ---- Stage out: 9 coalesced float4 stores per thread ----
#pragma unroll
    for (int i = 0; i < VEC_PER_THREAD; i++) {
        int li = threadIdx.x + i * THREADS;
        out[base_vec + li] = sv[li];
    }
}

// Scalar tail kernel for rows not covered by full 1024-row blocks.
__global__ void inv3_tail_kernel(const float* __restrict__ in,
                                 float* __restrict__ out, int nrows)
{
    int row = blockIdx.x * blockDim.x + threadIdx.x;
    if (row >= nrows) return;
    const float* p = in + (long long)row * 9;
    float* q = out + (long long)row * 9;

    float a = p[0], b = p[1], c = p[2];
    float d = p[4], e = p[5];
    float f = p[8];

    float ia  = __frcp_rn(a);
    float id  = __frcp_rn(d);
    float iff = __frcp_rn(f);

    float iad = ia * id;
    q[0] = ia;
    q[1] = -b * iad;
    q[2] = (b * e - c * d) * (iad * iff);
    q[3] = 0.0f;
    q[4] = id;
    q[5] = -e * (id * iff);
    q[6] = 0.0f;
    q[7] = 0.0f;
    q[8] = iff;
}

extern "C" void kernel_launch(void* const* d_in, const int* in_sizes, int n_in,
                              void* d_out, int out_size)
{
    const float* x = (const float*)d_in[0];
    float* y = (float*)d_out;
    long long total_floats = in_sizes[0];
    long long nrows = total_floats / 9;

    long long nblocks = nrows / ROWS_PER_BLOCK;
    if (nblocks > 0) {
        inv3_vec_kernel<<<(unsigned)nblocks, THREADS>>>(
            (const float4*)x, (float4*)y);
    }
    long long done = nblocks * ROWS_PER_BLOCK;
    int rem = (int)(nrows - done);
    if (rem > 0) {
        inv3_tail_kernel<<<(rem + 255) / 256, 256>>>(
            x + done * 9, y + done * 9, rem);
    }
}

// round 2
// speedup vs baseline: 1.1484x; 1.1484x over previous
#include <cuda_runtime.h>
#include <cuda_bf16.h>
#include <cstdint>

// Batched inverse of 3x3 upper-triangular matrices, rows of 9 fp32.
//   in : [a b c | . d e | . . f]
//   out: [1/a  -b/(ad)  (be-cd)/(adf) | 0  1/d  -e/(df) | 0 0 1/f]
//
// DRAM-bound streaming op (604 MB total). R2 change vs R1: tile shrunk from
// 1024 rows/36KB smem (6 CTAs/SM, 48 warps) to 256 rows/9KB smem so 8 CTAs/SM
// = 64 warps fit. Smaller sync phases + more independent CTAs per SM keep the
// DRAM queue full through the load->compute->store phase turnarounds.
//
// Coalescing: all global traffic is LDG.128/STG.128, block-contiguous.
// Smem banks: staging = consecutive float4 (conflict-free); compute reads
// word 9*t+k, gcd(9,32)=1 -> all 32 lanes distinct banks.

#define THREADS 256
#define ROWS_PER_BLOCK 256
#define FLOATS_PER_BLOCK (ROWS_PER_BLOCK * 9)   // 2304
#define VEC_PER_BLOCK (FLOATS_PER_BLOCK / 4)    // 576

__global__ __launch_bounds__(THREADS, 8) void inv3_vec_kernel(
    const float4* __restrict__ in, float4* __restrict__ out)
{
    __shared__ float s[FLOATS_PER_BLOCK];  // 9216 B

    const long long base_vec = (long long)blockIdx.x * VEC_PER_BLOCK;
    float4* sv = reinterpret_cast<float4*>(s);

    // ---- Stage in: 576 float4, 2-3 per thread, fully coalesced ----
#pragma unroll
    for (int i = 0; i < 3; i++) {
        int li = threadIdx.x + i * THREADS;
        if (li < VEC_PER_BLOCK)
            sv[li] = in[base_vec + li];
    }
    __syncthreads();

    // ---- Compute: 1 row per thread ----
    {
        float* p = &s[threadIdx.x * 9];
        float a = p[0], b = p[1], c = p[2];
        float d = p[4], e = p[5];
        float f = p[8];

        float ia  = __frcp_rn(a);
        float id  = __frcp_rn(d);
        float iff = __frcp_rn(f);

        float iad = ia * id;
        float o01 = -b * iad;
        float o12 = -e * (id * iff);
        float o02 = (b * e - c * d) * (iad * iff);

        p[0] = ia;
        p[1] = o01;
        p[2] = o02;
        p[3] = 0.0f;
        p[4] = id;
        p[5] = o12;
        p[6] = 0.0f;
        p[7] = 0.0f;
        p[8] = iff;
    }
    __syncthreads();

    // ---- Stage out: 576 float4, fully coalesced ----
#pragma unroll
    for (int i = 0; i < 3; i++) {
        int li = threadIdx.x + i * THREADS;
        if (li < VEC_PER_BLOCK)
            out[base_vec + li] = sv[li];
    }
}

// Scalar tail for rows not covered by full blocks (not hit for N=8388608).
__global__ void inv3_tail_kernel(const float* __restrict__ in,
                                 float* __restrict__ out, int nrows)
{
    int row = blockIdx.x * blockDim.x + threadIdx.x;
    if (row >= nrows) return;
    const float* p = in + (long long)row * 9;
    float* q = out + (long long)row * 9;

    float a = p[0], b = p[1], c = p[2];
    float d = p[4], e = p[5];
    float f = p[8];

    float ia  = __frcp_rn(a);
    float id  = __frcp_rn(d);
    float iff = __frcp_rn(f);

    float iad = ia * id;
    q[0] = ia;
    q[1] = -b * iad;
    q[2] = (b * e - c * d) * (iad * iff);
    q[3] = 0.0f;
    q[4] = id;
    q[5] = -e * (id * iff);
    q[6] = 0.0f;
    q[7] = 0.0f;
    q[8] = iff;
}

extern "C" void kernel_launch(void* const* d_in, const int* in_sizes, int n_in,
                              void* d_out, int out_size)
{
    const float* x = (const float*)d_in[0];
    float* y = (float*)d_out;
    long long total_floats = in_sizes[0];
    long long nrows = total_floats / 9;

    long long nblocks = nrows / ROWS_PER_BLOCK;
    if (nblocks > 0) {
        inv3_vec_kernel<<<(unsigned)nblocks, THREADS>>>(
            (const float4*)x, (float4*)y);
    }
    long long done = nblocks * ROWS_PER_BLOCK;
    int rem = (int)(nrows - done);
    if (rem > 0) {
        inv3_tail_kernel<<<(rem + 255) / 256, 256>>>(
            x + done * 9, y + done * 9, rem);
    }
}